// round 12
// baseline (speedup 1.0000x reference)
#include <cuda_runtime.h>
#include <math.h>

// QSP expectation Re(<0|U|0>) = f(cos x); f even parity, degree 54 in c
// => f = sum_{j=0}^{27} d_j T_j(y), y = cos(2x)
// => f(y) = G(u) + y*H(u), u = 2y^2-1 = cos(4x),
//    g_m = d_{2m};  h_0 = sum_m (-1)^m d_{2m+1}, h_k = 2 sum_{m>=k} (-1)^(m-k) d_{2m+1}.
// Fused kernel, latency-overlapped:
//  - element data PREFETCHED at kernel entry (LDG in flight through the prologue)
//  - 148 blocks x 896 threads: one CTA/SM, one wave, 148 redundant prologues
//  - prologue: parallel SU(2) chunks, distributed 28-pt DCT, even/odd split
//  - eval: packed fp32x2 FMA, 4 chains x 13 steps, coeffs float2 in shared

#define NSTEPS 54
#define NPH    55
#define NNODE  28
#define NCHUNK 9
#define CSTEP  6
#define NHALF  14
#define TPB    896

typedef unsigned long long u64;

__device__ __forceinline__ u64 pack2(float lo, float hi) {
    u64 r; asm("mov.b64 %0, {%1, %2};" : "=l"(r) : "f"(lo), "f"(hi)); return r;
}
__device__ __forceinline__ void unpack2(u64 v, float& lo, float& hi) {
    asm("mov.b64 {%0, %1}, %2;" : "=f"(lo), "=f"(hi) : "l"(v));
}
__device__ __forceinline__ u64 fma2(u64 a, u64 b, u64 c) {
    u64 d; asm("fma.rn.f32x2 %0, %1, %2, %3;" : "=l"(d) : "l"(a), "l"(b), "l"(c)); return d;
}
__device__ __forceinline__ u64 add2(u64 a, u64 b) {
    u64 d; asm("add.rn.f32x2 %0, %1, %2;" : "=l"(d) : "l"(a), "l"(b)); return d;
}

#define SU2_COMPOSE(a_r,a_i,b_r,b_i, alr,ali,ber,bei) do {                   \
    float nar = a_r*alr - a_i*ali - b_r*ber - b_i*bei;                       \
    float nai = a_r*ali + a_i*alr + b_r*bei - b_i*ber;                       \
    float nbr = a_r*ber - a_i*bei + b_r*alr + b_i*ali;                       \
    float nbi = a_r*bei + a_i*ber + b_i*alr - b_r*ali;                       \
    a_r = nar; a_i = nai; b_r = nbr; b_i = nbi;                              \
} while (0)

__global__ void __launch_bounds__(TPB) qsp_fused(
    const float4* __restrict__ x4,
    const float*  __restrict__ p,
    const float4* __restrict__ a4,
    const float*  __restrict__ bias,
    float4* __restrict__ out4,
    int n4)
{
    __shared__ float  ph[NPH];
    __shared__ float4 chunk[NNODE * NCHUNK];
    __shared__ float  fsh[NNODE];
    __shared__ float  psum[NNODE * 4];
    __shared__ float  dsh[NNODE];
    __shared__ float2 gsh[NHALF];
    __shared__ float2 hsh[NHALF];
    const float PI = 3.14159265358979323846f;
    int tid = threadIdx.x;

    // ---- Prefetch element data FIRST: loads stay in flight during the whole
    // prologue (scoreboard covers them; barriers don't drain LDG).
    int i = blockIdx.x * TPB + tid;
    int li = i < n4 ? i : (n4 - 1);                 // clamp: loads always legal
    float4 xv, av;
    float b0;
    {
        const float4* xp = x4 + li;
        const float4* ap = a4 + li;
        asm volatile("ld.global.nc.v4.f32 {%0,%1,%2,%3}, [%4];"
                     : "=f"(xv.x), "=f"(xv.y), "=f"(xv.z), "=f"(xv.w) : "l"(xp));
        asm volatile("ld.global.nc.v4.f32 {%0,%1,%2,%3}, [%4];"
                     : "=f"(av.x), "=f"(av.y), "=f"(av.z), "=f"(av.w) : "l"(ap));
        asm volatile("ld.global.nc.f32 %0, [%1];" : "=f"(b0) : "l"(bias));
    }

    if (tid < NPH) ph[tid] = p[tid];
    __syncthreads();

    // Phase 1: 252 threads, each a 6-step SU(2) partial product at node m.
    if (tid < NNODE * NCHUNK) {
        int m = tid / NCHUNK;
        int j = tid % NCHUNK;
        float th = PI * ((float)m + 0.5f) / 56.0f;     // y_m = cos(2*th)
        float cm, sm;
        __sincosf(th, &sm, &cm);
        float myph[CSTEP];
        #pragma unroll
        for (int s = 0; s < CSTEP; s++) myph[s] = ph[1 + j * CSTEP + s];
        float er, ei;
        __sincosf(myph[0], &ei, &er);
        float a_r = cm * er, a_i = cm * ei;            // C = M_first
        float b_r = sm * ei, b_i = sm * er;
        #pragma unroll
        for (int s = 1; s < CSTEP; s++) {
            __sincosf(myph[s], &ei, &er);
            float alr = cm * er, ali = cm * ei;        // alpha = c*e
            float ber = sm * ei, bei = sm * er;        // beta  = i*s*conj(e)
            SU2_COMPOSE(a_r, a_i, b_r, b_i, alr, ali, ber, bei);
        }
        chunk[tid] = make_float4(a_r, a_i, b_r, b_i);
    }
    __syncthreads();

    // Phase 2: per-node ordered composition of 9 chunks.
    if (tid < NNODE) {
        float4 Mv[NCHUNK];
        #pragma unroll
        for (int j = 0; j < NCHUNK; j++) Mv[j] = chunk[tid * NCHUNK + j];
        float a_r = Mv[0].x, a_i = Mv[0].y, b_r = Mv[0].z, b_i = Mv[0].w;
        #pragma unroll
        for (int j = 1; j < NCHUNK; j++)
            SU2_COMPOSE(a_r, a_i, b_r, b_i, Mv[j].x, Mv[j].y, Mv[j].z, Mv[j].w);
        float c0, s0;
        __sincosf(ph[0], &s0, &c0);
        fsh[tid] = c0 * a_r - s0 * a_i;                // f(theta_m)
    }
    __syncthreads();

    // Phase 3a: 28-pt DCT over 112 threads (4 partials of 7 terms per j).
    // Exact integer angle reduction: cos(pi*r/56) = -cos(pi*r/56 - pi), r mod 112.
    if (tid < NNODE * 4) {
        int j = tid >> 2;
        int q = tid & 3;
        float s = 0.f;
        int m0 = q * 7;
        #pragma unroll
        for (int m = m0; m < m0 + 7; m++) {
            int r = (j * (2 * m + 1)) % 112;
            float ang = (PI / 56.0f) * (float)r - PI;
            s = fmaf(fsh[m], -__cosf(ang), s);
        }
        psum[tid] = s;
    }
    __syncthreads();

    // Phase 3b: reduce partials -> d_j.
    if (tid < NNODE) {
        float s = ((psum[tid * 4] + psum[tid * 4 + 1]) +
                   (psum[tid * 4 + 2] + psum[tid * 4 + 3])) * (2.0f / (float)NNODE);
        if (tid == 0) s *= 0.5f;
        dsh[tid] = s;
    }
    __syncthreads();

    // Phase 4: even/odd split (exact integer weights), fully unrolled.
    if (tid < NHALF) {
        float g = dsh[2 * tid];
        gsh[tid] = make_float2(g, g);
        float h = 0.f, sign = 1.f;
        #pragma unroll
        for (int m = 0; m < NHALF; m++) {
            if (m >= tid) {
                h = fmaf(sign, dsh[2 * m + 1], h);
                sign = -sign;
            }
        }
        if (tid > 0) h *= 2.0f;
        hsh[tid] = make_float2(h, h);
    }
    __syncthreads();

    // Eval: 4 elems/thread, packed f32x2, 4 independent 13-step Clenshaw chains.
    float y0 = __cosf(2.0f * xv.x), y1 = __cosf(2.0f * xv.y);
    float y2 = __cosf(2.0f * xv.z), y3 = __cosf(2.0f * xv.w);

    u64 neg1 = pack2(-1.f, -1.f);
    u64 yP = pack2(y0, y1), yQ = pack2(y2, y3);
    u64 uP = fma2(add2(yP, yP), yP, neg1);         // u = 2y^2 - 1
    u64 uQ = fma2(add2(yQ, yQ), yQ, neg1);
    u64 tuP = add2(uP, uP), tuQ = add2(uQ, uQ);

    u64 gb1P = 0, gb2P = 0, hb1P = 0, hb2P = 0;
    u64 gb1Q = 0, gb2Q = 0, hb1Q = 0, hb2Q = 0;

    #pragma unroll
    for (int k = NHALF - 1; k >= 1; k--) {
        float2 gt = gsh[k];
        float2 ht = hsh[k];
        u64 gk, hk;
        asm("mov.b64 %0, {%1, %2};" : "=l"(gk) : "f"(gt.x), "f"(gt.y));
        asm("mov.b64 %0, {%1, %2};" : "=l"(hk) : "f"(ht.x), "f"(ht.y));
        u64 ngP = fma2(tuP, gb1P, fma2(neg1, gb2P, gk));
        u64 nhP = fma2(tuP, hb1P, fma2(neg1, hb2P, hk));
        u64 ngQ = fma2(tuQ, gb1Q, fma2(neg1, gb2Q, gk));
        u64 nhQ = fma2(tuQ, hb1Q, fma2(neg1, hb2Q, hk));
        gb2P = gb1P; gb1P = ngP;  hb2P = hb1P; hb1P = nhP;
        gb2Q = gb1Q; gb1Q = ngQ;  hb2Q = hb1Q; hb1Q = nhQ;
    }

    float2 g0t = gsh[0], h0t = hsh[0];
    u64 g0k, h0k;
    asm("mov.b64 %0, {%1, %2};" : "=l"(g0k) : "f"(g0t.x), "f"(g0t.y));
    asm("mov.b64 %0, {%1, %2};" : "=l"(h0k) : "f"(h0t.x), "f"(h0t.y));

    u64 GP = fma2(uP, gb1P, fma2(neg1, gb2P, g0k));
    u64 HP = fma2(uP, hb1P, fma2(neg1, hb2P, h0k));
    u64 GQ = fma2(uQ, gb1Q, fma2(neg1, gb2Q, g0k));
    u64 HQ = fma2(uQ, hb1Q, fma2(neg1, hb2Q, h0k));

    u64 fP = fma2(yP, HP, GP);                     // f = G + y*H
    u64 fQ = fma2(yQ, HQ, GQ);

    u64 aP = pack2(av.x, av.y), aQ = pack2(av.z, av.w);
    u64 bP = pack2(b0, b0);
    u64 oP = fma2(aP, fP, bP);
    u64 oQ = fma2(aQ, fQ, bP);

    if (i < n4) {
        float4 o;
        unpack2(oP, o.x, o.y);
        unpack2(oQ, o.z, o.w);
        out4[i] = o;
    }
}

extern "C" void kernel_launch(void* const* d_in, const int* in_sizes, int n_in,
                              void* d_out, int out_size) {
    const float* x    = (const float*)d_in[0];
    const float* p    = (const float*)d_in[1];
    const float* al   = (const float*)d_in[2];
    const float* bias = (const float*)d_in[3];

    int n4 = out_size / 4;                          // 131072
    int blocks = (n4 + TPB - 1) / TPB;              // 147
    if (blocks < 148) blocks = 148;                 // one CTA per SM, one wave
    qsp_fused<<<blocks, TPB>>>((const float4*)x, p, (const float4*)al, bias,
                               (float4*)d_out, n4);
}